// round 10
// baseline (speedup 1.0000x reference)
#include <cuda_runtime.h>
#include <math.h>
#include <cstdint>

#define S_TOK 4096
#define NH    12
#define HD    64
#define NROWS (S_TOK*NH)
#define QTILE 128
#define KTILE 32
#define NTILES (S_TOK/KTILE)
#define NSPLIT 3

// SMEM geometry (floats / bytes); triple-buffered K and V
#define KSTR 68
#define VSTR 72
#define QSTR 76
#define K_OFF   0
#define K_BUF_B (32*KSTR*4)
#define V_OFF   (3*K_BUF_B)
#define V_BUF_B (32*VSTR*4)
#define QP_OFF  (V_OFF + 3*V_BUF_B)
#define SMEM_BYTES (QP_OFF + 128*QSTR*4)

// ---------------- scratch ---------------------------------------------------
__device__ float g_k[(size_t)NH*S_TOK*HD];    // [h][s][d'] dims permuted in 8-groups
__device__ float g_v[(size_t)NH*S_TOK*HD];    // [h][s][d]  natural
__device__ float g_osc[(size_t)NSPLIT*S_TOK*NH*HD];  // partial O (unnormalized)
__device__ float2 g_ml[(size_t)NSPLIT*S_TOK*NH];     // per-row (m, l), log2 domain
__device__ float g_P[4][16];
__device__ float g_PT[4][16];
__device__ float g_Pinv[4][16];
__device__ float g_cos[32][8];
__device__ float g_sin[32][8];

__device__ __forceinline__ float tf32r(float x) {
    float r; asm("cvt.rna.tf32.f32 %0,%1;" : "=f"(r) : "f"(x)); return r;
}
__device__ __forceinline__ float ex2(float x) {
    float y; asm("ex2.approx.ftz.f32 %0,%1;" : "=f"(y) : "f"(x)); return y;
}
__device__ __forceinline__ uint32_t smem_u32(const void* p) {
    uint32_t a;
    asm("{ .reg .u64 t; cvta.to.shared.u64 t, %1; cvt.u32.u64 %0, t; }" : "=r"(a) : "l"(p));
    return a;
}
__device__ __forceinline__ void cp16(uint32_t dst, const void* src) {
    asm volatile("cp.async.cg.shared.global [%0], [%1], 16;" :: "r"(dst), "l"(src) : "memory");
}
#define CP_COMMIT() asm volatile("cp.async.commit_group;" ::: "memory")
#define CP_WAIT0()  asm volatile("cp.async.wait_group 0;" ::: "memory")
#define CP_WAIT1()  asm volatile("cp.async.wait_group 1;" ::: "memory")

__device__ __forceinline__ void mma_tf32(float* d, const uint32_t* a, float b0f, float b1f) {
    uint32_t b0 = __float_as_uint(b0f), b1 = __float_as_uint(b1f);
    asm volatile("mma.sync.aligned.m16n8k8.row.col.f32.tf32.tf32.f32 "
        "{%0,%1,%2,%3}, {%4,%5,%6,%7}, {%8,%9}, {%0,%1,%2,%3};"
        : "+f"(d[0]), "+f"(d[1]), "+f"(d[2]), "+f"(d[3])
        : "r"(a[0]), "r"(a[1]), "r"(a[2]), "r"(a[3]), "r"(b0), "r"(b1));
}

__device__ __forceinline__ void mm4(const float* A, const float* B, float* Cm) {
#pragma unroll
    for (int i = 0; i < 4; i++)
#pragma unroll
        for (int j = 0; j < 4; j++) {
            float s = 0.f;
#pragma unroll
            for (int kk = 0; kk < 4; kk++) s += A[i*4+kk] * B[kk*4+j];
            Cm[i*4+j] = s;
        }
}

// key permutation within 8-group (GEMM1 D-layout == GEMM2 A-layout)
__device__ __forceinline__ int kperm(int row) {
    int b = row & 7;
    int pb = (b < 4) ? (b << 1) : (((b - 4) << 1) | 1);
    return (row & ~7) | pb;
}

// ---------------------------------------------------------------------------
__global__ void prep_kernel(const float* __restrict__ vm, const float* __restrict__ Ks) {
    int t = threadIdx.x;
    if (t < 32) {
        float L = log2f(100.0f);
#pragma unroll
        for (int i = 0; i < 8; i++) {
            float f = exp2f(-L * (float)i / 8.0f);
            float sv, cv; sincosf((float)t * f, &sv, &cv);
            g_cos[t][i] = cv; g_sin[t][i] = sv;
        }
    }
    if (t < 4) {
        int c = t;
        const float* V  = vm + c*16;
        const float* Kc = Ks + c*9;
        float a = Kc[0] * (1.0f/512.0f);
        float b = Kc[4] * (1.0f/512.0f);
        float u = Kc[2] * (1.0f/512.0f) - 0.5f;
        float w = Kc[5] * (1.0f/512.0f) - 0.5f;
        float K4[16] = {a,0,u,0, 0,b,w,0, 0,0,1,0, 0,0,0,1};
        float Vl[16];
#pragma unroll
        for (int i = 0; i < 16; i++) Vl[i] = V[i];
        float P[16];
        mm4(K4, Vl, P);
#pragma unroll
        for (int i = 0; i < 4; i++)
#pragma unroll
            for (int jj = 0; jj < 4; jj++) { g_P[c][i*4+jj] = P[i*4+jj]; g_PT[c][i*4+jj] = P[jj*4+i]; }
        float Sm[16];
#pragma unroll
        for (int i = 0; i < 3; i++)
#pragma unroll
            for (int jj = 0; jj < 3; jj++) Sm[i*4+jj] = Vl[jj*4+i];
#pragma unroll
        for (int i = 0; i < 3; i++)
            Sm[i*4+3] = -(Sm[i*4+0]*Vl[3] + Sm[i*4+1]*Vl[7] + Sm[i*4+2]*Vl[11]);
        Sm[12]=0.f; Sm[13]=0.f; Sm[14]=0.f; Sm[15]=1.f;
        float Ki[16] = {1.0f/a,0,-u/a,0, 0,1.0f/b,-w/b,0, 0,0,1,0, 0,0,0,1};
        float Pi[16];
        mm4(Sm, Ki, Pi);
#pragma unroll
        for (int i = 0; i < 16; i++) g_Pinv[c][i] = Pi[i];
    }
}

// ---------------------------------------------------------------------------
__device__ __forceinline__ void transform_row_y(
    const float* __restrict__ in, float* __restrict__ y,
    const float* M, int px, int py)
{
    float x[64];
    const float4* in4 = (const float4*)in;
#pragma unroll
    for (int i = 0; i < 16; i++) {
        float4 tv = in4[i];
        x[4*i+0]=tv.x; x[4*i+1]=tv.y; x[4*i+2]=tv.z; x[4*i+3]=tv.w;
    }
#pragma unroll
    for (int g = 0; g < 8; g++)
#pragma unroll
        for (int i = 0; i < 4; i++)
            y[g*4+i] = M[i*4+0]*x[g*4+0] + M[i*4+1]*x[g*4+1]
                     + M[i*4+2]*x[g*4+2] + M[i*4+3]*x[g*4+3];
#pragma unroll
    for (int i = 0; i < 8; i++) {
        float c1 = g_cos[px][i], s1 = g_sin[px][i];
        y[32+i] =  c1*x[32+i] + s1*x[40+i];
        y[40+i] = -s1*x[32+i] + c1*x[40+i];
        float c2 = g_cos[py][i], s2 = g_sin[py][i];
        y[48+i] =  c2*x[48+i] + s2*x[56+i];
        y[56+i] = -s2*x[48+i] + c2*x[56+i];
    }
}

__global__ void transform_kv_kernel(const float* __restrict__ k, const float* __restrict__ v) {
    int r = blockIdx.x * blockDim.x + threadIdx.x;
    if (r >= NROWS) return;
    int s = r / NH;
    int h = r - s * NH;
    int c  = s >> 10;
    int px = s & 31;
    int py = (s >> 5) & 31;
    float M[16];
#pragma unroll
    for (int i = 0; i < 16; i++) M[i] = g_Pinv[c][i];
    size_t ibase = (size_t)r * HD;
    size_t obase = ((size_t)h * S_TOK + s) * HD;

    float y[64];
    // K: dim-permuted within 8-groups
    transform_row_y(k + ibase, y, M, px, py);
    {
        float4* o4 = (float4*)(g_k + obase);
#pragma unroll
        for (int i = 0; i < 16; i++) {
            int b = (i >> 1) * 8;
            if ((i & 1) == 0)
                o4[i] = make_float4(tf32r(y[b+0]), tf32r(y[b+4]), tf32r(y[b+1]), tf32r(y[b+5]));
            else
                o4[i] = make_float4(tf32r(y[b+2]), tf32r(y[b+6]), tf32r(y[b+3]), tf32r(y[b+7]));
        }
    }
    // V: natural order
    transform_row_y(v + ibase, y, M, px, py);
    {
        float4* o4 = (float4*)(g_v + obase);
#pragma unroll
        for (int i = 0; i < 16; i++)
            o4[i] = make_float4(tf32r(y[4*i+0]), tf32r(y[4*i+1]), tf32r(y[4*i+2]), tf32r(y[4*i+3]));
    }
}

// ---------------------------------------------------------------------------
// Pipelined flash attention over a KV slice (blockIdx.z selects the slice).
// Writes unnormalized partial O + per-row (m,l) to global scratch.
// ---------------------------------------------------------------------------

#define STAGE(BUF, T) do { \
    const float* ksrc_ = kg + (size_t)(T) * KTILE * HD; \
    const float* vsrc_ = vg + (size_t)(T) * KTILE * HD; \
    uint32_t kb_ = sb + K_OFF + (uint32_t)(BUF) * K_BUF_B; \
    uint32_t vb_ = sb + V_OFF + (uint32_t)(BUF) * V_BUF_B; \
    _Pragma("unroll") \
    for (int i_ = 0; i_ < 4; i_++) { \
        int idx_ = tid + i_*128; \
        int row_ = idx_ >> 4, ch_ = idx_ & 15; \
        cp16(kb_ + (uint32_t)(kperm(row_)*KSTR + ch_*4)*4, ksrc_ + idx_*4); \
        cp16(vb_ + (uint32_t)(row_*VSTR + ch_*4)*4, vsrc_ + idx_*4); \
    } \
    CP_COMMIT(); \
} while(0)

#define SOFTMAX(SCN) do { \
    _Pragma("unroll") \
    for (int m_ = 0; m_ < 2; m_++) \
    _Pragma("unroll") \
    for (int hi_ = 0; hi_ < 2; hi_++) { \
        int rc_ = m_*2 + hi_; \
        float mt_ = -1e30f; \
        _Pragma("unroll") \
        for (int nb_ = 0; nb_ < 4; nb_++) { \
            mt_ = fmaxf(mt_, SCN[m_][nb_][hi_*2]); \
            mt_ = fmaxf(mt_, SCN[m_][nb_][hi_*2+1]); \
        } \
        mt_ = fmaxf(mt_, __shfl_xor_sync(0xffffffffu, mt_, 1)); \
        mt_ = fmaxf(mt_, __shfl_xor_sync(0xffffffffu, mt_, 2)); \
        float mn_ = fmaxf(mrow[rc_], mt_); \
        rs[rc_] = ex2(mrow[rc_] - mn_); \
        mrow[rc_] = mn_; \
        float ps_ = 0.f; \
        _Pragma("unroll") \
        for (int nb_ = 0; nb_ < 4; nb_++) { \
            float p0_ = ex2(SCN[m_][nb_][hi_*2]   - mn_); \
            float p1_ = ex2(SCN[m_][nb_][hi_*2+1] - mn_); \
            ps_ += p0_ + p1_; \
            SCN[m_][nb_][hi_*2]   = tf32r(p0_); \
            SCN[m_][nb_][hi_*2+1] = tf32r(p1_); \
        } \
        ps_ += __shfl_xor_sync(0xffffffffu, ps_, 1); \
        ps_ += __shfl_xor_sync(0xffffffffu, ps_, 2); \
        lsum[rc_] = lsum[rc_]*rs[rc_] + ps_; \
    } \
} while(0)

#define RESCALE() do { \
    bool a1_ = (rs[0]==1.f) & (rs[1]==1.f) & (rs[2]==1.f) & (rs[3]==1.f); \
    if (!__all_sync(0xffffffffu, a1_)) { \
        _Pragma("unroll") \
        for (int m_ = 0; m_ < 2; m_++) \
        _Pragma("unroll") \
        for (int nb_ = 0; nb_ < 8; nb_++) { \
            o[m_][nb_][0] *= rs[m_*2];   o[m_][nb_][1] *= rs[m_*2]; \
            o[m_][nb_][2] *= rs[m_*2+1]; o[m_][nb_][3] *= rs[m_*2+1]; \
        } \
    } \
} while(0)

#define TILE_BODY(SCP, SCN) do { \
    CP_WAIT0(); __syncthreads(); \
    if (tnext < t1) { STAGE(bf, tnext); tnext++; } \
    const float* Kf_ = smf + (K_OFF/4) + bn*(K_BUF_B/4); \
    const float* Vf_ = smf + (V_OFF/4) + bc*(V_BUF_B/4); \
    _Pragma("unroll") \
    for (int m_ = 0; m_ < 2; m_++) \
    _Pragma("unroll") \
    for (int nb_ = 0; nb_ < 4; nb_++) \
    _Pragma("unroll") \
    for (int e_ = 0; e_ < 4; e_++) SCN[m_][nb_][e_] = 0.f; \
    RESCALE(); \
    _Pragma("unroll") \
    for (int st_ = 0; st_ < 4; st_++) { \
        _Pragma("unroll") \
        for (int u_ = 0; u_ < 2; u_++) { \
            int tt_ = 2*st_ + u_; \
            _Pragma("unroll") \
            for (int nb_ = 0; nb_ < 4; nb_++) { \
                float2 b_ = *(const float2*)&Kf_[(nb_*8 + g)*KSTR + tt_*8 + qcol]; \
                mma_tf32(SCN[0][nb_], qa[0][tt_], b_.x, b_.y); \
                mma_tf32(SCN[1][nb_], qa[1][tt_], b_.x, b_.y); \
            } \
        } \
        uint32_t pa0_[4] = {__float_as_uint(SCP[0][st_][0]), __float_as_uint(SCP[0][st_][2]), \
                            __float_as_uint(SCP[0][st_][1]), __float_as_uint(SCP[0][st_][3])}; \
        uint32_t pa1_[4] = {__float_as_uint(SCP[1][st_][0]), __float_as_uint(SCP[1][st_][2]), \
                            __float_as_uint(SCP[1][st_][1]), __float_as_uint(SCP[1][st_][3])}; \
        _Pragma("unroll") \
        for (int nb_ = 0; nb_ < 8; nb_++) { \
            const float* vr_ = Vf_ + (st_*8 + j)*VSTR + nb_*8 + g; \
            mma_tf32(o[0][nb_], pa0_, vr_[0], vr_[4*VSTR]); \
            mma_tf32(o[1][nb_], pa1_, vr_[0], vr_[4*VSTR]); \
        } \
    } \
    SOFTMAX(SCN); \
    { int tb_ = bc; bc = bn; bn = bf; bf = tb_; } \
} while(0)

__global__ void __launch_bounds__(QTILE)
attn_kernel(const float* __restrict__ q) {
    extern __shared__ char smraw[];
    const uint32_t sb = smem_u32(smraw);
    float* smf = (float*)smraw;
    float* QP  = (float*)(smraw + QP_OFF);

    const int tid  = threadIdx.x;
    const int w    = tid >> 5, lane = tid & 31;
    const int g    = lane >> 2, j = lane & 3;
    const int h    = blockIdx.y;
    const int z    = blockIdx.z;
    const int s    = blockIdx.x * QTILE + tid;
    const int cam  = s >> 10, px = s & 31, py = (s >> 5) & 31;
    const int qcol = 2*j;

    // KV tile range for this split: 44 / 42 / 42 (all even)
    const int t0 = (z == 0) ? 0 : (44 + (z - 1) * 42);
    const int t1 = t0 + ((z == 0) ? 44 : 42);

    const float* kg = g_k + (size_t)h * S_TOK * HD;
    const float* vg = g_v + (size_t)h * S_TOK * HD;

    STAGE(0, t0);
    STAGE(1, t0 + 1);

    // ---- Q transform -> SMEM (dim-permuted, scale*log2e folded) ----
    {
        float y[64];
        transform_row_y(q + (size_t)s * (NH*HD) + (size_t)h * HD, y, g_PT[cam], px, py);
        const float SC = 0.18033688011112042f;  // (1/8)*log2(e)
        float4* dst = (float4*)&QP[(size_t)tid*QSTR];
#pragma unroll
        for (int i = 0; i < 16; i++) {
            int b = (i >> 1) * 8;
            if ((i & 1) == 0)
                dst[i] = make_float4(tf32r(y[b+0]*SC), tf32r(y[b+4]*SC),
                                     tf32r(y[b+1]*SC), tf32r(y[b+5]*SC));
            else
                dst[i] = make_float4(tf32r(y[b+2]*SC), tf32r(y[b+6]*SC),
                                     tf32r(y[b+3]*SC), tf32r(y[b+7]*SC));
        }
    }
    CP_WAIT1();
    __syncthreads();

    // ---- persistent Q A-fragments ----
    uint32_t qa[2][8][4];
    {
        const int r00 = w*32 + g;
#pragma unroll
        for (int tt = 0; tt < 8; tt++) {
            float2 f00 = *(const float2*)&QP[(r00   )*QSTR + tt*8 + qcol];
            float2 f01 = *(const float2*)&QP[(r00+ 8)*QSTR + tt*8 + qcol];
            float2 f10 = *(const float2*)&QP[(r00+16)*QSTR + tt*8 + qcol];
            float2 f11 = *(const float2*)&QP[(r00+24)*QSTR + tt*8 + qcol];
            qa[0][tt][0] = __float_as_uint(f00.x); qa[0][tt][1] = __float_as_uint(f01.x);
            qa[0][tt][2] = __float_as_uint(f00.y); qa[0][tt][3] = __float_as_uint(f01.y);
            qa[1][tt][0] = __float_as_uint(f10.x); qa[1][tt][1] = __float_as_uint(f11.x);
            qa[1][tt][2] = __float_as_uint(f10.y); qa[1][tt][3] = __float_as_uint(f11.y);
        }
    }

    float o[2][8][4];
#pragma unroll
    for (int m = 0; m < 2; m++)
#pragma unroll
        for (int nb = 0; nb < 8; nb++)
#pragma unroll
            for (int e = 0; e < 4; e++) o[m][nb][e] = 0.f;
    float mrow[4] = {-1e30f, -1e30f, -1e30f, -1e30f};
    float lsum[4] = {0.f, 0.f, 0.f, 0.f};
    float rs[4];
    float scA[2][4][4], scB[2][4][4];
    int bc = 0, bn = 1, bf = 2;
    int tnext = t0 + 2;

    // ---- preamble: GEMM1(t0) + softmax into scA ----
    {
        const float* Kf_ = smf + (K_OFF/4);
#pragma unroll
        for (int m = 0; m < 2; m++)
#pragma unroll
            for (int nb = 0; nb < 4; nb++)
#pragma unroll
                for (int e = 0; e < 4; e++) scA[m][nb][e] = 0.f;
#pragma unroll
        for (int tt = 0; tt < 8; tt++)
#pragma unroll
            for (int nb = 0; nb < 4; nb++) {
                float2 b = *(const float2*)&Kf_[(nb*8 + g)*KSTR + tt*8 + qcol];
                mma_tf32(scA[0][nb], qa[0][tt], b.x, b.y);
                mma_tf32(scA[1][nb], qa[1][tt], b.x, b.y);
            }
        SOFTMAX(scA);
    }

    // ---- pipelined main loop: NT-1 bodies (NT even -> odd count) ----
    const int npairs = (t1 - t0 - 2) / 2;
    TILE_BODY(scA, scB);
#pragma unroll 1
    for (int i = 0; i < npairs; i++) {
        TILE_BODY(scB, scA);
        TILE_BODY(scA, scB);
    }

    // ---- final: rescale + GEMM2(last) from scB ----
    {
        const float* Vf_ = smf + (V_OFF/4) + bc*(V_BUF_B/4);
        RESCALE();
#pragma unroll
        for (int st = 0; st < 4; st++) {
            uint32_t pa0[4] = {__float_as_uint(scB[0][st][0]), __float_as_uint(scB[0][st][2]),
                               __float_as_uint(scB[0][st][1]), __float_as_uint(scB[0][st][3])};
            uint32_t pa1[4] = {__float_as_uint(scB[1][st][0]), __float_as_uint(scB[1][st][2]),
                               __float_as_uint(scB[1][st][1]), __float_as_uint(scB[1][st][3])};
#pragma unroll
            for (int nb = 0; nb < 8; nb++) {
                const float* vr = Vf_ + (st*8 + j)*VSTR + nb*8 + g;
                mma_tf32(o[0][nb], pa0, vr[0], vr[4*VSTR]);
                mma_tf32(o[1][nb], pa1, vr[0], vr[4*VSTR]);
            }
        }
    }

    // ---- write per-row (m,l) for combine (j==0 lanes own unique rows) ----
    if (j == 0) {
#pragma unroll
        for (int m = 0; m < 2; m++)
#pragma unroll
            for (int hi = 0; hi < 2; hi++) {
                int rc = m*2 + hi;
                int srow = blockIdx.x*QTILE + w*32 + m*16 + hi*8 + g;
                g_ml[(size_t)z*S_TOK*NH + (size_t)srow*NH + h] = make_float2(mrow[rc], lsum[rc]);
            }
    }

    // ---- exchange unnormalized O through SMEM, write partial to scratch ----
    __syncthreads();
#pragma unroll
    for (int m = 0; m < 2; m++) {
        int r0 = w*32 + m*16 + g, r1 = r0 + 8;
#pragma unroll
        for (int nb = 0; nb < 8; nb++) {
            *(float2*)&QP[r0*QSTR + nb*8 + 2*j] = make_float2(o[m][nb][0], o[m][nb][1]);
            *(float2*)&QP[r1*QSTR + nb*8 + 2*j] = make_float2(o[m][nb][2], o[m][nb][3]);
        }
    }
    __syncthreads();
    {
        float4* dst = (float4*)(g_osc + ((size_t)z*S_TOK*NH + (size_t)s*NH + h) * HD);
        const float4* src = (const float4*)&QP[(size_t)tid*QSTR];
#pragma unroll
        for (int i = 0; i < 16; i++) dst[i] = src[i];
    }
}

// ---------------------------------------------------------------------------
// Combine: merge NSPLIT partials (exact flash merge) + output epilogue.
// ---------------------------------------------------------------------------
__global__ void __launch_bounds__(128)
combine_kernel(float* __restrict__ out) {
    int r = blockIdx.x * 128 + threadIdx.x;   // r = s*NH + h
    int s = r / NH;
    int cam = s >> 10, px = s & 31, py = (s >> 5) & 31;

    float2 ml0 = g_ml[(size_t)0*S_TOK*NH + r];
    float2 ml1 = g_ml[(size_t)1*S_TOK*NH + r];
    float2 ml2 = g_ml[(size_t)2*S_TOK*NH + r];
    float M = fmaxf(ml0.x, fmaxf(ml1.x, ml2.x));
    float w0 = ex2(ml0.x - M), w1 = ex2(ml1.x - M), w2 = ex2(ml2.x - M);
    float inv = 1.0f / (ml0.y*w0 + ml1.y*w1 + ml2.y*w2);
    w0 *= inv; w1 *= inv; w2 *= inv;

    const float4* p0 = (const float4*)(g_osc + ((size_t)0*S_TOK*NH + r) * HD);
    const float4* p1 = (const float4*)(g_osc + ((size_t)1*S_TOK*NH + r) * HD);
    const float4* p2 = (const float4*)(g_osc + ((size_t)2*S_TOK*NH + r) * HD);
    float acc[64];
#pragma unroll
    for (int i = 0; i < 16; i++) {
        float4 a = p0[i], b = p1[i], c = p2[i];
        acc[4*i+0] = a.x*w0 + b.x*w1 + c.x*w2;
        acc[4*i+1] = a.y*w0 + b.y*w1 + c.y*w2;
        acc[4*i+2] = a.z*w0 + b.z*w1 + c.z*w2;
        acc[4*i+3] = a.w*w0 + b.w*w1 + c.w*w2;
    }

    // epilogue: to() = P proj + inverse RoPE
    float y[64];
    const float* Mx = g_P[cam];
#pragma unroll
    for (int gg = 0; gg < 8; gg++)
#pragma unroll
        for (int i = 0; i < 4; i++)
            y[gg*4+i] = Mx[i*4+0]*acc[gg*4+0] + Mx[i*4+1]*acc[gg*4+1]
                      + Mx[i*4+2]*acc[gg*4+2] + Mx[i*4+3]*acc[gg*4+3];
#pragma unroll
    for (int i = 0; i < 8; i++) {
        float c1 = g_cos[px][i], s1 = g_sin[px][i];
        y[32+i] = c1*acc[32+i] - s1*acc[40+i];
        y[40+i] = s1*acc[32+i] + c1*acc[40+i];
        float c2 = g_cos[py][i], s2 = g_sin[py][i];
        y[48+i] = c2*acc[48+i] - s2*acc[56+i];
        y[56+i] = s2*acc[48+i] + c2*acc[56+i];
    }
    float4* o4 = (float4*)(out + (size_t)r * HD);
#pragma unroll
    for (int i = 0; i < 16; i++)
        o4[i] = make_float4(y[4*i+0], y[4*i+1], y[4*i+2], y[4*i+3]);
}

// ---------------------------------------------------------------------------
extern "C" void kernel_launch(void* const* d_in, const int* in_sizes, int n_in,
                              void* d_out, int out_size) {
    const float* q  = (const float*)d_in[0];
    const float* k  = (const float*)d_in[1];
    const float* v  = (const float*)d_in[2];
    const float* vm = (const float*)d_in[3];
    const float* Ks = (const float*)d_in[4];
    float* out = (float*)d_out;

    cudaFuncSetAttribute(attn_kernel, cudaFuncAttributeMaxDynamicSharedMemorySize, SMEM_BYTES);

    prep_kernel<<<1, 32>>>(vm, Ks);
    transform_kv_kernel<<<(NROWS + 255) / 256, 256>>>(k, v);
    attn_kernel<<<dim3(S_TOK / QTILE, NH, NSPLIT), QTILE, SMEM_BYTES>>>(q);
    combine_kernel<<<NROWS / 128, 128>>>(out);
}

// round 11
// speedup vs baseline: 1.0097x; 1.0097x over previous
#include <cuda_runtime.h>
#include <math.h>
#include <cstdint>

#define S_TOK 4096
#define NH    12
#define HD    64
#define NROWS (S_TOK*NH)
#define QTILE 128
#define KTILE 32
#define NTILES (S_TOK/KTILE)

// SMEM geometry (floats / bytes); triple-buffered K and V
#define KSTR 68
#define VSTR 72
#define QSTR 76
#define K_OFF   0
#define K_BUF_B (32*KSTR*4)
#define V_OFF   (3*K_BUF_B)
#define V_BUF_B (32*VSTR*4)
#define QP_OFF  (V_OFF + 3*V_BUF_B)
#define SMEM_BYTES (QP_OFF + 128*QSTR*4)   // 92672 -> 2 CTAs/SM

// ---------------- scratch ---------------------------------------------------
__device__ float g_k[(size_t)NH*S_TOK*HD];   // [h][s][d'] dims permuted in 8-groups
__device__ float g_v[(size_t)NH*S_TOK*HD];   // [h][s][d]  natural
__device__ float g_P[4][16];
__device__ float g_PT[4][16];
__device__ float g_Pinv[4][16];
__device__ float g_cos[32][8];
__device__ float g_sin[32][8];

__device__ __forceinline__ float tf32r(float x) {
    float r; asm("cvt.rna.tf32.f32 %0,%1;" : "=f"(r) : "f"(x)); return r;
}
__device__ __forceinline__ float ex2(float x) {
    float y; asm("ex2.approx.ftz.f32 %0,%1;" : "=f"(y) : "f"(x)); return y;
}
__device__ __forceinline__ uint32_t smem_u32(const void* p) {
    uint32_t a;
    asm("{ .reg .u64 t; cvta.to.shared.u64 t, %1; cvt.u32.u64 %0, t; }" : "=r"(a) : "l"(p));
    return a;
}
__device__ __forceinline__ void cp16(uint32_t dst, const void* src) {
    asm volatile("cp.async.cg.shared.global [%0], [%1], 16;" :: "r"(dst), "l"(src) : "memory");
}
#define CP_COMMIT() asm volatile("cp.async.commit_group;" ::: "memory")
#define CP_WAIT0()  asm volatile("cp.async.wait_group 0;" ::: "memory")
#define CP_WAIT1()  asm volatile("cp.async.wait_group 1;" ::: "memory")

__device__ __forceinline__ void mma_tf32(float* d, const uint32_t* a, float b0f, float b1f) {
    uint32_t b0 = __float_as_uint(b0f), b1 = __float_as_uint(b1f);
    asm volatile("mma.sync.aligned.m16n8k8.row.col.f32.tf32.tf32.f32 "
        "{%0,%1,%2,%3}, {%4,%5,%6,%7}, {%8,%9}, {%0,%1,%2,%3};"
        : "+f"(d[0]), "+f"(d[1]), "+f"(d[2]), "+f"(d[3])
        : "r"(a[0]), "r"(a[1]), "r"(a[2]), "r"(a[3]), "r"(b0), "r"(b1));
}

__device__ __forceinline__ void mm4(const float* A, const float* B, float* Cm) {
#pragma unroll
    for (int i = 0; i < 4; i++)
#pragma unroll
        for (int j = 0; j < 4; j++) {
            float s = 0.f;
#pragma unroll
            for (int kk = 0; kk < 4; kk++) s += A[i*4+kk] * B[kk*4+j];
            Cm[i*4+j] = s;
        }
}

// key permutation within 8-group (GEMM1 D-layout == GEMM2 A-layout)
__device__ __forceinline__ int kperm(int row) {
    int b = row & 7;
    int pb = (b < 4) ? (b << 1) : (((b - 4) << 1) | 1);
    return (row & ~7) | pb;
}

// ---------------------------------------------------------------------------
__global__ void prep_kernel(const float* __restrict__ vm, const float* __restrict__ Ks) {
    int t = threadIdx.x;
    if (t < 32) {
        float L = log2f(100.0f);
#pragma unroll
        for (int i = 0; i < 8; i++) {
            float f = exp2f(-L * (float)i / 8.0f);
            float sv, cv; sincosf((float)t * f, &sv, &cv);
            g_cos[t][i] = cv; g_sin[t][i] = sv;
        }
    }
    if (t < 4) {
        int c = t;
        const float* V  = vm + c*16;
        const float* Kc = Ks + c*9;
        float a = Kc[0] * (1.0f/512.0f);
        float b = Kc[4] * (1.0f/512.0f);
        float u = Kc[2] * (1.0f/512.0f) - 0.5f;
        float w = Kc[5] * (1.0f/512.0f) - 0.5f;
        float K4[16] = {a,0,u,0, 0,b,w,0, 0,0,1,0, 0,0,0,1};
        float Vl[16];
#pragma unroll
        for (int i = 0; i < 16; i++) Vl[i] = V[i];
        float P[16];
        mm4(K4, Vl, P);
#pragma unroll
        for (int i = 0; i < 4; i++)
#pragma unroll
            for (int jj = 0; jj < 4; jj++) { g_P[c][i*4+jj] = P[i*4+jj]; g_PT[c][i*4+jj] = P[jj*4+i]; }
        float Sm[16];
#pragma unroll
        for (int i = 0; i < 3; i++)
#pragma unroll
            for (int jj = 0; jj < 3; jj++) Sm[i*4+jj] = Vl[jj*4+i];
#pragma unroll
        for (int i = 0; i < 3; i++)
            Sm[i*4+3] = -(Sm[i*4+0]*Vl[3] + Sm[i*4+1]*Vl[7] + Sm[i*4+2]*Vl[11]);
        Sm[12]=0.f; Sm[13]=0.f; Sm[14]=0.f; Sm[15]=1.f;
        float Ki[16] = {1.0f/a,0,-u/a,0, 0,1.0f/b,-w/b,0, 0,0,1,0, 0,0,0,1};
        float Pi[16];
        mm4(Sm, Ki, Pi);
#pragma unroll
        for (int i = 0; i < 16; i++) g_Pinv[c][i] = Pi[i];
    }
}

// ---------------------------------------------------------------------------
__device__ __forceinline__ void transform_row_y(
    const float* __restrict__ in, float* __restrict__ y,
    const float* M, int px, int py)
{
    float x[64];
    const float4* in4 = (const float4*)in;
#pragma unroll
    for (int i = 0; i < 16; i++) {
        float4 tv = in4[i];
        x[4*i+0]=tv.x; x[4*i+1]=tv.y; x[4*i+2]=tv.z; x[4*i+3]=tv.w;
    }
#pragma unroll
    for (int g = 0; g < 8; g++)
#pragma unroll
        for (int i = 0; i < 4; i++)
            y[g*4+i] = M[i*4+0]*x[g*4+0] + M[i*4+1]*x[g*4+1]
                     + M[i*4+2]*x[g*4+2] + M[i*4+3]*x[g*4+3];
#pragma unroll
    for (int i = 0; i < 8; i++) {
        float c1 = g_cos[px][i], s1 = g_sin[px][i];
        y[32+i] =  c1*x[32+i] + s1*x[40+i];
        y[40+i] = -s1*x[32+i] + c1*x[40+i];
        float c2 = g_cos[py][i], s2 = g_sin[py][i];
        y[48+i] =  c2*x[48+i] + s2*x[56+i];
        y[56+i] = -s2*x[48+i] + c2*x[56+i];
    }
}

__global__ void transform_kv_kernel(const float* __restrict__ k, const float* __restrict__ v) {
    int r = blockIdx.x * blockDim.x + threadIdx.x;
    if (r >= NROWS) return;
    int s = r / NH;
    int h = r - s * NH;
    int c  = s >> 10;
    int px = s & 31;
    int py = (s >> 5) & 31;
    float M[16];
#pragma unroll
    for (int i = 0; i < 16; i++) M[i] = g_Pinv[c][i];
    size_t ibase = (size_t)r * HD;
    size_t obase = ((size_t)h * S_TOK + s) * HD;

    float y[64];
    // K: dim-permuted within 8-groups
    transform_row_y(k + ibase, y, M, px, py);
    {
        float4* o4 = (float4*)(g_k + obase);
#pragma unroll
        for (int i = 0; i < 16; i++) {
            int b = (i >> 1) * 8;
            if ((i & 1) == 0)
                o4[i] = make_float4(tf32r(y[b+0]), tf32r(y[b+4]), tf32r(y[b+1]), tf32r(y[b+5]));
            else
                o4[i] = make_float4(tf32r(y[b+2]), tf32r(y[b+6]), tf32r(y[b+3]), tf32r(y[b+7]));
        }
    }
    // V: natural order
    transform_row_y(v + ibase, y, M, px, py);
    {
        float4* o4 = (float4*)(g_v + obase);
#pragma unroll
        for (int i = 0; i < 16; i++)
            o4[i] = make_float4(tf32r(y[4*i+0]), tf32r(y[4*i+1]), tf32r(y[4*i+2]), tf32r(y[4*i+3]));
    }
}

// ---------------------------------------------------------------------------
// Pipelined flash attention. Body order per tile t:
//   GEMM1(t+1) -> RESCALE(rs from softmax(t)) -> SOFTMAX(t+1) -> GEMM2(t)
// SOFTMAX and GEMM2 are data-independent and share one basic block, so the
// scheduler fills the softmax dependency-chain stalls with GEMM2 mma/LDS.
// ---------------------------------------------------------------------------

#define STAGE(BUF, T) do { \
    const float* ksrc_ = kg + (size_t)(T) * KTILE * HD; \
    const float* vsrc_ = vg + (size_t)(T) * KTILE * HD; \
    uint32_t kb_ = sb + K_OFF + (uint32_t)(BUF) * K_BUF_B; \
    uint32_t vb_ = sb + V_OFF + (uint32_t)(BUF) * V_BUF_B; \
    _Pragma("unroll") \
    for (int i_ = 0; i_ < 4; i_++) { \
        int idx_ = tid + i_*128; \
        int row_ = idx_ >> 4, ch_ = idx_ & 15; \
        cp16(kb_ + (uint32_t)(kperm(row_)*KSTR + ch_*4)*4, ksrc_ + idx_*4); \
        cp16(vb_ + (uint32_t)(row_*VSTR + ch_*4)*4, vsrc_ + idx_*4); \
    } \
    CP_COMMIT(); \
} while(0)

#define SOFTMAX(SCN) do { \
    _Pragma("unroll") \
    for (int m_ = 0; m_ < 2; m_++) \
    _Pragma("unroll") \
    for (int hi_ = 0; hi_ < 2; hi_++) { \
        int rc_ = m_*2 + hi_; \
        float mt_ = -1e30f; \
        _Pragma("unroll") \
        for (int nb_ = 0; nb_ < 4; nb_++) { \
            mt_ = fmaxf(mt_, SCN[m_][nb_][hi_*2]); \
            mt_ = fmaxf(mt_, SCN[m_][nb_][hi_*2+1]); \
        } \
        mt_ = fmaxf(mt_, __shfl_xor_sync(0xffffffffu, mt_, 1)); \
        mt_ = fmaxf(mt_, __shfl_xor_sync(0xffffffffu, mt_, 2)); \
        float mn_ = fmaxf(mrow[rc_], mt_); \
        rs[rc_] = ex2(mrow[rc_] - mn_); \
        mrow[rc_] = mn_; \
        float ps_ = 0.f; \
        _Pragma("unroll") \
        for (int nb_ = 0; nb_ < 4; nb_++) { \
            float p0_ = ex2(SCN[m_][nb_][hi_*2]   - mn_); \
            float p1_ = ex2(SCN[m_][nb_][hi_*2+1] - mn_); \
            ps_ += p0_ + p1_; \
            SCN[m_][nb_][hi_*2]   = tf32r(p0_); \
            SCN[m_][nb_][hi_*2+1] = tf32r(p1_); \
        } \
        ps_ += __shfl_xor_sync(0xffffffffu, ps_, 1); \
        ps_ += __shfl_xor_sync(0xffffffffu, ps_, 2); \
        lsum[rc_] = lsum[rc_]*rs[rc_] + ps_; \
    } \
} while(0)

#define RESCALE() do { \
    bool a1_ = (rs[0]==1.f) & (rs[1]==1.f) & (rs[2]==1.f) & (rs[3]==1.f); \
    if (!__all_sync(0xffffffffu, a1_)) { \
        _Pragma("unroll") \
        for (int m_ = 0; m_ < 2; m_++) \
        _Pragma("unroll") \
        for (int nb_ = 0; nb_ < 8; nb_++) { \
            o[m_][nb_][0] *= rs[m_*2];   o[m_][nb_][1] *= rs[m_*2]; \
            o[m_][nb_][2] *= rs[m_*2+1]; o[m_][nb_][3] *= rs[m_*2+1]; \
        } \
    } \
} while(0)

#define GEMM2(SCP, VFP) do { \
    _Pragma("unroll") \
    for (int st_ = 0; st_ < 4; st_++) { \
        uint32_t pa0_[4] = {__float_as_uint(SCP[0][st_][0]), __float_as_uint(SCP[0][st_][2]), \
                            __float_as_uint(SCP[0][st_][1]), __float_as_uint(SCP[0][st_][3])}; \
        uint32_t pa1_[4] = {__float_as_uint(SCP[1][st_][0]), __float_as_uint(SCP[1][st_][2]), \
                            __float_as_uint(SCP[1][st_][1]), __float_as_uint(SCP[1][st_][3])}; \
        _Pragma("unroll") \
        for (int nb_ = 0; nb_ < 8; nb_++) { \
            const float* vr_ = (VFP) + (st_*8 + j)*VSTR + nb_*8 + g; \
            mma_tf32(o[0][nb_], pa0_, vr_[0], vr_[4*VSTR]); \
            mma_tf32(o[1][nb_], pa1_, vr_[0], vr_[4*VSTR]); \
        } \
    } \
} while(0)

#define TILE_BODY(T, SCP, SCN) do { \
    CP_WAIT0(); __syncthreads(); \
    if ((T)+2 < NTILES) STAGE(bf, (T)+2); \
    const float* Kf_ = smf + (K_OFF/4) + bn*(K_BUF_B/4); \
    const float* Vf_ = smf + (V_OFF/4) + bc*(V_BUF_B/4); \
    _Pragma("unroll") \
    for (int m_ = 0; m_ < 2; m_++) \
    _Pragma("unroll") \
    for (int nb_ = 0; nb_ < 4; nb_++) \
    _Pragma("unroll") \
    for (int e_ = 0; e_ < 4; e_++) SCN[m_][nb_][e_] = 0.f; \
    /* GEMM1(t+1): complete as early as possible */ \
    _Pragma("unroll") \
    for (int tt_ = 0; tt_ < 8; tt_++) \
    _Pragma("unroll") \
    for (int nb_ = 0; nb_ < 4; nb_++) { \
        float2 b_ = *(const float2*)&Kf_[(nb_*8 + g)*KSTR + tt_*8 + qcol]; \
        mma_tf32(SCN[0][nb_], qa[0][tt_], b_.x, b_.y); \
        mma_tf32(SCN[1][nb_], qa[1][tt_], b_.x, b_.y); \
    } \
    /* rescale with OLD rs (branchy part kept before softmax/GEMM2 region) */ \
    RESCALE(); \
    /* softmax(t+1) and GEMM2(t) are independent -> scheduler interleaves */ \
    SOFTMAX(SCN); \
    GEMM2(SCP, Vf_); \
    { int tb_ = bc; bc = bn; bn = bf; bf = tb_; } \
} while(0)

__global__ void __launch_bounds__(QTILE)
attn_kernel(const float* __restrict__ q, float* __restrict__ out) {
    extern __shared__ char smraw[];
    const uint32_t sb = smem_u32(smraw);
    float* smf = (float*)smraw;
    float* QP  = (float*)(smraw + QP_OFF);

    const int tid  = threadIdx.x;
    const int w    = tid >> 5, lane = tid & 31;
    const int g    = lane >> 2, j = lane & 3;
    const int h    = blockIdx.y;
    const int s    = blockIdx.x * QTILE + tid;
    const int cam  = s >> 10, px = s & 31, py = (s >> 5) & 31;
    const int qcol = 2*j;

    const float* kg = g_k + (size_t)h * S_TOK * HD;
    const float* vg = g_v + (size_t)h * S_TOK * HD;

    STAGE(0, 0);
    STAGE(1, 1);

    // ---- Q transform -> SMEM (dim-permuted, scale*log2e folded) ----
    {
        float y[64];
        transform_row_y(q + (size_t)s * (NH*HD) + (size_t)h * HD, y, g_PT[cam], px, py);
        const float SC = 0.18033688011112042f;  // (1/8)*log2(e)
        float4* dst = (float4*)&QP[(size_t)tid*QSTR];
#pragma unroll
        for (int i = 0; i < 16; i++) {
            int b = (i >> 1) * 8;
            if ((i & 1) == 0)
                dst[i] = make_float4(tf32r(y[b+0]*SC), tf32r(y[b+4]*SC),
                                     tf32r(y[b+1]*SC), tf32r(y[b+5]*SC));
            else
                dst[i] = make_float4(tf32r(y[b+2]*SC), tf32r(y[b+6]*SC),
                                     tf32r(y[b+3]*SC), tf32r(y[b+7]*SC));
        }
    }
    CP_WAIT1();
    __syncthreads();   // QP visible; K/V tile0 visible

    // ---- persistent Q A-fragments (LDS.64, permuted cols) ----
    uint32_t qa[2][8][4];
    {
        const int r00 = w*32 + g;
#pragma unroll
        for (int tt = 0; tt < 8; tt++) {
            float2 f00 = *(const float2*)&QP[(r00   )*QSTR + tt*8 + qcol];
            float2 f01 = *(const float2*)&QP[(r00+ 8)*QSTR + tt*8 + qcol];
            float2 f10 = *(const float2*)&QP[(r00+16)*QSTR + tt*8 + qcol];
            float2 f11 = *(const float2*)&QP[(r00+24)*QSTR + tt*8 + qcol];
            qa[0][tt][0] = __float_as_uint(f00.x); qa[0][tt][1] = __float_as_uint(f01.x);
            qa[0][tt][2] = __float_as_uint(f00.y); qa[0][tt][3] = __float_as_uint(f01.y);
            qa[1][tt][0] = __float_as_uint(f10.x); qa[1][tt][1] = __float_as_uint(f11.x);
            qa[1][tt][2] = __float_as_uint(f10.y); qa[1][tt][3] = __float_as_uint(f11.y);
        }
    }

    float o[2][8][4];
#pragma unroll
    for (int m = 0; m < 2; m++)
#pragma unroll
        for (int nb = 0; nb < 8; nb++)
#pragma unroll
            for (int e = 0; e < 4; e++) o[m][nb][e] = 0.f;
    float mrow[4] = {-1e30f, -1e30f, -1e30f, -1e30f};
    float lsum[4] = {0.f, 0.f, 0.f, 0.f};
    float rs[4];
    float scA[2][4][4], scB[2][4][4];
    int bc = 0, bn = 1, bf = 2;

    // ---- preamble: GEMM1(0) + softmax(0) into scA ----
    {
        const float* Kf_ = smf + (K_OFF/4);
#pragma unroll
        for (int m = 0; m < 2; m++)
#pragma unroll
            for (int nb = 0; nb < 4; nb++)
#pragma unroll
                for (int e = 0; e < 4; e++) scA[m][nb][e] = 0.f;
#pragma unroll
        for (int tt = 0; tt < 8; tt++)
#pragma unroll
            for (int nb = 0; nb < 4; nb++) {
                float2 b = *(const float2*)&Kf_[(nb*8 + g)*KSTR + tt*8 + qcol];
                mma_tf32(scA[0][nb], qa[0][tt], b.x, b.y);
                mma_tf32(scA[1][nb], qa[1][tt], b.x, b.y);
            }
        SOFTMAX(scA);
    }

    // ---- pipelined main loop ----
#pragma unroll 1
    for (int t = 0; t < NTILES-2; t += 2) {
        TILE_BODY(t,   scA, scB);
        TILE_BODY(t+1, scB, scA);
    }
    TILE_BODY(NTILES-2, scA, scB);

    // ---- final tile: rescale + GEMM2(127) ----
    {
        const float* Vf_ = smf + (V_OFF/4) + bc*(V_BUF_B/4);
        RESCALE();
        GEMM2(scB, Vf_);
    }

    // ---- normalize, exchange O through SMEM, epilogue ----
    __syncthreads();
    float inv[4];
#pragma unroll
    for (int rc = 0; rc < 4; rc++) inv[rc] = 1.0f / lsum[rc];
#pragma unroll
    for (int m = 0; m < 2; m++) {
        int r0 = w*32 + m*16 + g, r1 = r0 + 8;
#pragma unroll
        for (int nb = 0; nb < 8; nb++) {
            *(float2*)&QP[r0*QSTR + nb*8 + 2*j] =
                make_float2(o[m][nb][0]*inv[m*2],   o[m][nb][1]*inv[m*2]);
            *(float2*)&QP[r1*QSTR + nb*8 + 2*j] =
                make_float2(o[m][nb][2]*inv[m*2+1], o[m][nb][3]*inv[m*2+1]);
        }
    }
    __syncthreads();

    {
        float acc[64];
#pragma unroll
        for (int i = 0; i < 16; i++) {
            float4 tv = *(const float4*)&QP[(size_t)tid*QSTR + i*4];
            acc[4*i+0]=tv.x; acc[4*i+1]=tv.y; acc[4*i+2]=tv.z; acc[4*i+3]=tv.w;
        }
        float y[64];
        const float* M = g_P[cam];
#pragma unroll
        for (int gg = 0; gg < 8; gg++)
#pragma unroll
            for (int i = 0; i < 4; i++)
                y[gg*4+i] = M[i*4+0]*acc[gg*4+0] + M[i*4+1]*acc[gg*4+1]
                          + M[i*4+2]*acc[gg*4+2] + M[i*4+3]*acc[gg*4+3];
#pragma unroll
        for (int i = 0; i < 8; i++) {
            float c1 = g_cos[px][i], s1 = g_sin[px][i];
            y[32+i] = c1*acc[32+i] - s1*acc[40+i];
            y[40+i] = s1*acc[32+i] + c1*acc[40+i];
            float c2 = g_cos[py][i], s2 = g_sin[py][i];
            y[48+i] = c2*acc[48+i] - s2*acc[56+i];
            y[56+i] = s2*acc[48+i] + c2*acc[56+i];
        }
        float4* o4 = (float4*)(out + (size_t)s * (NH*HD) + (size_t)h * HD);
#pragma unroll
        for (int i = 0; i < 16; i++)
            o4[i] = make_float4(y[4*i+0], y[4*i+1], y[4*i+2], y[4*i+3]);
    }
}

// ---------------------------------------------------------------------------
extern "C" void kernel_launch(void* const* d_in, const int* in_sizes, int n_in,
                              void* d_out, int out_size) {
    const float* q  = (const float*)d_in[0];
    const float* k  = (const float*)d_in[1];
    const float* v  = (const float*)d_in[2];
    const float* vm = (const float*)d_in[3];
    const float* Ks = (const float*)d_in[4];
    float* out = (float*)d_out;

    cudaFuncSetAttribute(attn_kernel, cudaFuncAttributeMaxDynamicSharedMemorySize, SMEM_BYTES);

    prep_kernel<<<1, 32>>>(vm, Ks);
    transform_kv_kernel<<<(NROWS + 255) / 256, 256>>>(k, v);
    attn_kernel<<<dim3(S_TOK / QTILE, NH), QTILE, SMEM_BYTES>>>(q, out);
}

// round 12
// speedup vs baseline: 1.6964x; 1.6801x over previous
#include <cuda_runtime.h>
#include <cuda_fp16.h>
#include <math.h>
#include <cstdint>

#define S_TOK 4096
#define NH    12
#define HD    64
#define NROWS (S_TOK*NH)
#define QTILE 128
#define KTILE 32
#define NTILES (S_TOK/KTILE)

// SMEM geometry (bytes). Row stride 160B -> bank = 8g+2j per phase (conflict-free)
#define ROWB   160
#define K_BUF_B (32*ROWB)               // 5120
#define V_BUF_B (64*ROWB)               // 10240
#define K_OFF   0
#define V_OFF   (3*K_BUF_B)             // 15360
#define QF_OFF  (V_OFF + 3*V_BUF_B)     // 46080
#define SMEM_BYTES (QF_OFF + 128*ROWB)  // 66560
#define QSTR 76                          // fp32 O-exchange stride (reuses K/V region)

// ---------------- scratch ---------------------------------------------------
__device__ __half g_k[(size_t)NH*S_TOK*HD];   // [h][s][d'] fp16, dims permuted in 16-groups
__device__ __half g_vt[(size_t)NH*HD*S_TOK];  // [h][d][s]  fp16, keys permuted in 16-groups
__device__ float g_P[4][16];
__device__ float g_PT[4][16];
__device__ float g_Pinv[4][16];
__device__ float g_cos[32][8];
__device__ float g_sin[32][8];

__device__ __forceinline__ float ex2(float x) {
    float y; asm("ex2.approx.ftz.f32 %0,%1;" : "=f"(y) : "f"(x)); return y;
}
__device__ __forceinline__ uint32_t smem_u32(const void* p) {
    uint32_t a;
    asm("{ .reg .u64 t; cvta.to.shared.u64 t, %1; cvt.u32.u64 %0, t; }" : "=r"(a) : "l"(p));
    return a;
}
__device__ __forceinline__ void cp16(uint32_t dst, const void* src) {
    asm volatile("cp.async.cg.shared.global [%0], [%1], 16;" :: "r"(dst), "l"(src) : "memory");
}
#define CP_COMMIT() asm volatile("cp.async.commit_group;" ::: "memory")
#define CP_WAIT0()  asm volatile("cp.async.wait_group 0;" ::: "memory")
#define CP_WAIT1()  asm volatile("cp.async.wait_group 1;" ::: "memory")

// pack two fp32 -> fp16x2 (lo, hi)
__device__ __forceinline__ uint32_t packh2(float lo, float hi) {
    uint32_t d; asm("cvt.rn.f16x2.f32 %0, %1, %2;" : "=r"(d) : "f"(hi), "f"(lo)); return d;
}

// m16n8k16 fp16 mma, fp32 accumulate in place
__device__ __forceinline__ void mma_f16(float* d, const uint32_t* a, uint32_t b0, uint32_t b1) {
    asm volatile("mma.sync.aligned.m16n8k16.row.col.f32.f16.f16.f32 "
        "{%0,%1,%2,%3}, {%4,%5,%6,%7}, {%8,%9}, {%0,%1,%2,%3};"
        : "+f"(d[0]), "+f"(d[1]), "+f"(d[2]), "+f"(d[3])
        : "r"(a[0]), "r"(a[1]), "r"(a[2]), "r"(a[3]), "r"(b0), "r"(b1));
}

__device__ __forceinline__ void mm4(const float* A, const float* B, float* Cm) {
#pragma unroll
    for (int i = 0; i < 4; i++)
#pragma unroll
        for (int j = 0; j < 4; j++) {
            float s = 0.f;
#pragma unroll
            for (int kk = 0; kk < 4; kk++) s += A[i*4+kk] * B[kk*4+j];
            Cm[i*4+j] = s;
        }
}

// ---------------------------------------------------------------------------
__global__ void prep_kernel(const float* __restrict__ vm, const float* __restrict__ Ks) {
    int t = threadIdx.x;
    if (t < 32) {
        float L = log2f(100.0f);
#pragma unroll
        for (int i = 0; i < 8; i++) {
            float f = exp2f(-L * (float)i / 8.0f);
            float sv, cv; sincosf((float)t * f, &sv, &cv);
            g_cos[t][i] = cv; g_sin[t][i] = sv;
        }
    }
    if (t < 4) {
        int c = t;
        const float* V  = vm + c*16;
        const float* Kc = Ks + c*9;
        float a = Kc[0] * (1.0f/512.0f);
        float b = Kc[4] * (1.0f/512.0f);
        float u = Kc[2] * (1.0f/512.0f) - 0.5f;
        float w = Kc[5] * (1.0f/512.0f) - 0.5f;
        float K4[16] = {a,0,u,0, 0,b,w,0, 0,0,1,0, 0,0,0,1};
        float Vl[16];
#pragma unroll
        for (int i = 0; i < 16; i++) Vl[i] = V[i];
        float P[16];
        mm4(K4, Vl, P);
#pragma unroll
        for (int i = 0; i < 4; i++)
#pragma unroll
            for (int jj = 0; jj < 4; jj++) { g_P[c][i*4+jj] = P[i*4+jj]; g_PT[c][i*4+jj] = P[jj*4+i]; }
        float Sm[16];
#pragma unroll
        for (int i = 0; i < 3; i++)
#pragma unroll
            for (int jj = 0; jj < 3; jj++) Sm[i*4+jj] = Vl[jj*4+i];
#pragma unroll
        for (int i = 0; i < 3; i++)
            Sm[i*4+3] = -(Sm[i*4+0]*Vl[3] + Sm[i*4+1]*Vl[7] + Sm[i*4+2]*Vl[11]);
        Sm[12]=0.f; Sm[13]=0.f; Sm[14]=0.f; Sm[15]=1.f;
        float Ki[16] = {1.0f/a,0,-u/a,0, 0,1.0f/b,-w/b,0, 0,0,1,0, 0,0,0,1};
        float Pi[16];
        mm4(Sm, Ki, Pi);
#pragma unroll
        for (int i = 0; i < 16; i++) g_Pinv[c][i] = Pi[i];
    }
}

// ---------------------------------------------------------------------------
__device__ __forceinline__ void transform_row_y(
    const float* __restrict__ in, float* __restrict__ y,
    const float* M, int px, int py)
{
    float x[64];
    const float4* in4 = (const float4*)in;
#pragma unroll
    for (int i = 0; i < 16; i++) {
        float4 tv = in4[i];
        x[4*i+0]=tv.x; x[4*i+1]=tv.y; x[4*i+2]=tv.z; x[4*i+3]=tv.w;
    }
#pragma unroll
    for (int g = 0; g < 8; g++)
#pragma unroll
        for (int i = 0; i < 4; i++)
            y[g*4+i] = M[i*4+0]*x[g*4+0] + M[i*4+1]*x[g*4+1]
                     + M[i*4+2]*x[g*4+2] + M[i*4+3]*x[g*4+3];
#pragma unroll
    for (int i = 0; i < 8; i++) {
        float c1 = g_cos[px][i], s1 = g_sin[px][i];
        y[32+i] =  c1*x[32+i] + s1*x[40+i];
        y[40+i] = -s1*x[32+i] + c1*x[40+i];
        float c2 = g_cos[py][i], s2 = g_sin[py][i];
        y[48+i] =  c2*x[48+i] + s2*x[56+i];
        y[56+i] = -s2*x[48+i] + c2*x[56+i];
    }
}

// warp = one 32-token tile of one head (r = h*4096 + s)
__global__ void transform_kv_kernel(const float* __restrict__ k, const float* __restrict__ v) {
    __shared__ __half vsm[8][64][33];
    int tid = threadIdx.x;
    int r = blockIdx.x * 256 + tid;
    int w = tid >> 5, lane = tid & 31;
    int h = r >> 12;
    int s = r & 4095;
    int cam = s >> 10, px = s & 31, py = (s >> 5) & 31;
    float M[16];
#pragma unroll
    for (int i = 0; i < 16; i++) M[i] = g_Pinv[cam][i];
    size_t ibase = ((size_t)s * NH + h) * HD;

    float y[64];
    // ---- K: dim-permuted in 16-groups, fp16, coalesced row store ----
    transform_row_y(k + ibase, y, M, px, py);
    {
        uint32_t kk[32];
#pragma unroll
        for (int t = 0; t < 4; t++)
#pragma unroll
            for (int jj = 0; jj < 4; jj++) {
                int base = t*16, q = t*4 + jj;
                kk[2*q]   = packh2(y[base+2*jj],   y[base+2*jj+1]);
                kk[2*q+1] = packh2(y[base+2*jj+8], y[base+2*jj+9]);
            }
        uint4* o4 = (uint4*)(g_k + ((size_t)h*S_TOK + s)*HD);
#pragma unroll
        for (int i = 0; i < 8; i++) o4[i] = ((uint4*)kk)[i];
    }
    // ---- V: transpose through SMEM -> g_vt[h][d][s], keys permuted in 16-groups ----
    transform_row_y(v + ibase, y, M, px, py);
#pragma unroll
    for (int d = 0; d < 64; d++) vsm[w][d][lane] = __float2half(y[d]);
    __syncwarp();
    int tile = s >> 5;
#pragma unroll
    for (int hf = 0; hf < 2; hf++) {
        int d = lane + 32*hf;
        uint32_t ov[16];
#pragma unroll
        for (int tk = 0; tk < 2; tk++)
#pragma unroll
            for (int q = 0; q < 4; q++) {
                int b = tk*8 + q*2;
                __half2 e = __halves2half2(vsm[w][d][tk*16+2*q],   vsm[w][d][tk*16+2*q+1]);
                __half2 f = __halves2half2(vsm[w][d][tk*16+8+2*q], vsm[w][d][tk*16+8+2*q+1]);
                ov[b]   = *(uint32_t*)&e;
                ov[b+1] = *(uint32_t*)&f;
            }
        uint4* dst = (uint4*)(g_vt + ((size_t)h*HD + d)*S_TOK + (size_t)tile*32);
#pragma unroll
        for (int i = 0; i < 4; i++) dst[i] = ((uint4*)ov)[i];
    }
}

// ---------------------------------------------------------------------------
// fp16 m16n8k16 pipelined flash attention. Triple-buffered K/VT (cp.async),
// P packs straight from GEMM1 D registers (no permutation, no SMEM trip).
// ---------------------------------------------------------------------------

#define STAGE(BUF, T) do { \
    uint32_t kb_ = sb + K_OFF + (uint32_t)(BUF) * K_BUF_B; \
    uint32_t vb_ = sb + V_OFF + (uint32_t)(BUF) * V_BUF_B; \
    const __half* ks_ = kg2 + (size_t)(T) * (KTILE*HD); \
    const __half* vs_ = vtg + (size_t)(T) * KTILE; \
    _Pragma("unroll") \
    for (int i_ = 0; i_ < 2; i_++) { \
        int idx_ = tid + i_*128; \
        int kr_ = idx_ >> 3, kc_ = idx_ & 7; \
        cp16(kb_ + (uint32_t)(kr_*ROWB + kc_*16), ks_ + kr_*HD + kc_*8); \
        int vr_ = idx_ >> 2, vc_ = idx_ & 3; \
        cp16(vb_ + (uint32_t)(vr_*ROWB + vc_*16), vs_ + (size_t)vr_*S_TOK + vc_*8); \
    } \
    CP_COMMIT(); \
} while(0)

#define SOFTMAX(SCN) do { \
    _Pragma("unroll") \
    for (int m_ = 0; m_ < 2; m_++) \
    _Pragma("unroll") \
    for (int hi_ = 0; hi_ < 2; hi_++) { \
        int rc_ = m_*2 + hi_; \
        float mt_ = -1e30f; \
        _Pragma("unroll") \
        for (int nb_ = 0; nb_ < 4; nb_++) { \
            mt_ = fmaxf(mt_, SCN[m_][nb_][hi_*2]); \
            mt_ = fmaxf(mt_, SCN[m_][nb_][hi_*2+1]); \
        } \
        mt_ = fmaxf(mt_, __shfl_xor_sync(0xffffffffu, mt_, 1)); \
        mt_ = fmaxf(mt_, __shfl_xor_sync(0xffffffffu, mt_, 2)); \
        float mn_ = fmaxf(mrow[rc_], mt_); \
        rs[rc_] = ex2(mrow[rc_] - mn_); \
        mrow[rc_] = mn_; \
        float ps_ = 0.f; \
        _Pragma("unroll") \
        for (int nb_ = 0; nb_ < 4; nb_++) { \
            float p0_ = ex2(SCN[m_][nb_][hi_*2]   - mn_); \
            float p1_ = ex2(SCN[m_][nb_][hi_*2+1] - mn_); \
            ps_ += p0_ + p1_; \
            SCN[m_][nb_][hi_*2]   = p0_; \
            SCN[m_][nb_][hi_*2+1] = p1_; \
        } \
        ps_ += __shfl_xor_sync(0xffffffffu, ps_, 1); \
        ps_ += __shfl_xor_sync(0xffffffffu, ps_, 2); \
        lsum[rc_] = lsum[rc_]*rs[rc_] + ps_; \
    } \
} while(0)

#define RESCALE() do { \
    bool a1_ = (rs[0]==1.f) & (rs[1]==1.f) & (rs[2]==1.f) & (rs[3]==1.f); \
    if (!__all_sync(0xffffffffu, a1_)) { \
        _Pragma("unroll") \
        for (int m_ = 0; m_ < 2; m_++) \
        _Pragma("unroll") \
        for (int nb_ = 0; nb_ < 8; nb_++) { \
            o[m_][nb_][0] *= rs[m_*2];   o[m_][nb_][1] *= rs[m_*2]; \
            o[m_][nb_][2] *= rs[m_*2+1]; o[m_][nb_][3] *= rs[m_*2+1]; \
        } \
    } \
} while(0)

#define GEMM1(SCN, KFP) do { \
    _Pragma("unroll") \
    for (int tt_ = 0; tt_ < 4; tt_++) \
    _Pragma("unroll") \
    for (int nb_ = 0; nb_ < 4; nb_++) { \
        uint2 b_ = *(const uint2*)((KFP) + (nb_*8 + g)*ROWB + tt_*32 + 8*j); \
        mma_f16(SCN[0][nb_], qa[0][tt_], b_.x, b_.y); \
        mma_f16(SCN[1][nb_], qa[1][tt_], b_.x, b_.y); \
    } \
} while(0)

#define GEMM2(SCP, VFP) do { \
    _Pragma("unroll") \
    for (int tk_ = 0; tk_ < 2; tk_++) { \
        uint32_t pa0_[4] = { packh2(SCP[0][2*tk_][0],   SCP[0][2*tk_][1]), \
                             packh2(SCP[0][2*tk_][2],   SCP[0][2*tk_][3]), \
                             packh2(SCP[0][2*tk_+1][0], SCP[0][2*tk_+1][1]), \
                             packh2(SCP[0][2*tk_+1][2], SCP[0][2*tk_+1][3]) }; \
        uint32_t pa1_[4] = { packh2(SCP[1][2*tk_][0],   SCP[1][2*tk_][1]), \
                             packh2(SCP[1][2*tk_][2],   SCP[1][2*tk_][3]), \
                             packh2(SCP[1][2*tk_+1][0], SCP[1][2*tk_+1][1]), \
                             packh2(SCP[1][2*tk_+1][2], SCP[1][2*tk_+1][3]) }; \
        _Pragma("unroll") \
        for (int nb_ = 0; nb_ < 8; nb_++) { \
            uint2 b_ = *(const uint2*)((VFP) + (nb_*8 + g)*ROWB + tk_*32 + 8*j); \
            mma_f16(o[0][nb_], pa0_, b_.x, b_.y); \
            mma_f16(o[1][nb_], pa1_, b_.x, b_.y); \
        } \
    } \
} while(0)

#define TILE_BODY(T, SCP, SCN) do { \
    CP_WAIT0(); __syncthreads(); \
    if ((T)+2 < NTILES) STAGE(bf, (T)+2); \
    const char* Kf_ = smraw + K_OFF + bn*K_BUF_B; \
    const char* Vf_ = smraw + V_OFF + bc*V_BUF_B; \
    _Pragma("unroll") \
    for (int m_ = 0; m_ < 2; m_++) \
    _Pragma("unroll") \
    for (int nb_ = 0; nb_ < 4; nb_++) \
    _Pragma("unroll") \
    for (int e_ = 0; e_ < 4; e_++) SCN[m_][nb_][e_] = 0.f; \
    GEMM1(SCN, Kf_); \
    RESCALE(); \
    SOFTMAX(SCN); \
    GEMM2(SCP, Vf_); \
    { int tb_ = bc; bc = bn; bn = bf; bf = tb_; } \
} while(0)

__global__ void __launch_bounds__(QTILE)
attn_kernel(const float* __restrict__ q, float* __restrict__ out) {
    extern __shared__ char smraw[];
    const uint32_t sb = smem_u32(smraw);

    const int tid  = threadIdx.x;
    const int w    = tid >> 5, lane = tid & 31;
    const int g    = lane >> 2, j = lane & 3;
    const int h    = blockIdx.y;
    const int s    = blockIdx.x * QTILE + tid;
    const int cam  = s >> 10, px = s & 31, py = (s >> 5) & 31;

    const __half* kg2 = g_k  + (size_t)h * S_TOK * HD;
    const __half* vtg = g_vt + (size_t)h * HD * S_TOK;

    STAGE(0, 0);
    STAGE(1, 1);

    // ---- Q transform -> QF (fp16, dim-permuted, scale*log2e folded) ----
    {
        float y[64];
        transform_row_y(q + (size_t)s * (NH*HD) + (size_t)h * HD, y, g_PT[cam], px, py);
        const float SC = 0.18033688011112042f;  // (1/8)*log2(e)
        uint32_t qq[32];
#pragma unroll
        for (int t = 0; t < 4; t++)
#pragma unroll
            for (int jj = 0; jj < 4; jj++) {
                int base = t*16, qx = t*4 + jj;
                qq[2*qx]   = packh2(y[base+2*jj]*SC,   y[base+2*jj+1]*SC);
                qq[2*qx+1] = packh2(y[base+2*jj+8]*SC, y[base+2*jj+9]*SC);
            }
        uint4* dst = (uint4*)(smraw + QF_OFF + tid*ROWB);
#pragma unroll
        for (int i = 0; i < 8; i++) dst[i] = ((uint4*)qq)[i];
    }
    CP_WAIT1();
    __syncthreads();

    // ---- persistent Q A-fragments (LDS.64 pairs) ----
    uint32_t qa[2][4][4];
#pragma unroll
    for (int m = 0; m < 2; m++)
#pragma unroll
        for (int tt = 0; tt < 4; tt++) {
            const char* rp = smraw + QF_OFF + (w*32 + m*16 + g)*ROWB + tt*32 + 8*j;
            uint2 lo = *(const uint2*)rp;
            uint2 hi = *(const uint2*)(rp + 8*ROWB);
            qa[m][tt][0] = lo.x; qa[m][tt][1] = hi.x;
            qa[m][tt][2] = lo.y; qa[m][tt][3] = hi.y;
        }

    float o[2][8][4];
#pragma unroll
    for (int m = 0; m < 2; m++)
#pragma unroll
        for (int nb = 0; nb < 8; nb++)
#pragma unroll
            for (int e = 0; e < 4; e++) o[m][nb][e] = 0.f;
    float mrow[4] = {-1e30f, -1e30f, -1e30f, -1e30f};
    float lsum[4] = {0.f, 0.f, 0.f, 0.f};
    float rs[4];
    float scA[2][4][4], scB[2][4][4];
    int bc = 0, bn = 1, bf = 2;

    // ---- preamble: GEMM1(0) + softmax(0) into scA ----
    {
        const char* Kf_ = smraw + K_OFF;
#pragma unroll
        for (int m = 0; m < 2; m++)
#pragma unroll
            for (int nb = 0; nb < 4; nb++)
#pragma unroll
                for (int e = 0; e < 4; e++) scA[m][nb][e] = 0.f;
        GEMM1(scA, Kf_);
        SOFTMAX(scA);
    }

    // ---- pipelined main loop ----
#pragma unroll 1
    for (int t = 0; t < NTILES-2; t += 2) {
        TILE_BODY(t,   scA, scB);
        TILE_BODY(t+1, scB, scA);
    }
    TILE_BODY(NTILES-2, scA, scB);

    // ---- final tile: rescale + GEMM2(127) ----
    {
        const char* Vf_ = smraw + V_OFF + bc*V_BUF_B;
        RESCALE();
        GEMM2(scB, Vf_);
    }

    // ---- normalize, exchange O through SMEM (reuse K/V region), epilogue ----
    __syncthreads();
    float* QP = (float*)smraw;
    float inv[4];
#pragma unroll
    for (int rc = 0; rc < 4; rc++) inv[rc] = 1.0f / lsum[rc];
#pragma unroll
    for (int m = 0; m < 2; m++) {
        int r0 = w*32 + m*16 + g, r1 = r0 + 8;
#pragma unroll
        for (int nb = 0; nb < 8; nb++) {
            *(float2*)&QP[r0*QSTR + nb*8 + 2*j] =
                make_float2(o[m][nb][0]*inv[m*2],   o[m][nb][1]*inv[m*2]);
            *(float2*)&QP[r1*QSTR + nb*8 + 2*j] =
                make_float2(o[m][nb][2]*inv[m*2+1], o[m][nb][3]*inv[m*2+1]);
        }
    }
    __syncthreads();

    {
        float acc[64];
#pragma unroll
        for (int i = 0; i < 16; i++) {
            float4 tv = *(const float4*)&QP[(size_t)tid*QSTR + i*4];
            acc[4*i+0]=tv.x; acc[4*i+1]=tv.y; acc[4*i+2]=tv.z; acc[4*i+3]=tv.w;
        }
        float y[64];
        const float* M = g_P[cam];
#pragma unroll
        for (int gg = 0; gg < 8; gg++)
#pragma unroll
            for (int i = 0; i < 4; i++)
                y[gg*4+i] = M[i*4+0]*acc[gg*4+0] + M[i*4+1]*acc[gg*4+1]
                          + M[i*4+2]*acc[gg*4+2] + M[i*4+3]*acc[gg*4+3];
#pragma unroll
        for (int i = 0; i < 8; i++) {
            float c1 = g_cos[px][i], s1 = g_sin[px][i];
            y[32+i] = c1*acc[32+i] - s1*acc[40+i];
            y[40+i] = s1*acc[32+i] + c1*acc[40+i];
            float c2 = g_cos[py][i], s2 = g_sin[py][i];
            y[48+i] = c2*acc[48+i] - s2*acc[56+i];
            y[56+i] = s2*acc[48+i] + c2*acc[56+i];
        }
        float4* o4 = (float4*)(out + (size_t)s * (NH*HD) + (size_t)h * HD);
#pragma unroll
        for (int i = 0; i < 16; i++)
            o4[i] = make_float4(y[4*i+0], y[4*i+1], y[4*i+2], y[4*i+3]);
    }
}

// ---------------------------------------------------------------------------
extern "C" void kernel_launch(void* const* d_in, const int* in_sizes, int n_in,
                              void* d_out, int out_size) {
    const float* q  = (const float*)d_in[0];
    const float* k  = (const float*)d_in[1];
    const float* v  = (const float*)d_in[2];
    const float* vm = (const float*)d_in[3];
    const float* Ks = (const float*)d_in[4];
    float* out = (float*)d_out;

    cudaFuncSetAttribute(attn_kernel, cudaFuncAttributeMaxDynamicSharedMemorySize, SMEM_BYTES);

    prep_kernel<<<1, 32>>>(vm, Ks);
    transform_kv_kernel<<<NROWS / 256, 256>>>(k, v);
    attn_kernel<<<dim3(S_TOK / QTILE, NH), QTILE, SMEM_BYTES>>>(q, out);
}